// round 7
// baseline (speedup 1.0000x reference)
#include <cuda_runtime.h>
#include <cuda_bf16.h>
#include <cstdint>

#define TT   2048
#define DD   64
#define CH   64
#define NC   (TT/CH)    // 32 chunks
#define BH   64         // B*H
#define PIT  72         // smem pitch (bf16 elems) for 64-col tiles
#define PIT2 40         // smem pitch (bf16 elems) for 32-col V tiles (conflict-free ldsm)
#define TILE_B (DD*PIT*2)   // 9216 B

// Exclusive-prefix KV states, fp32: 64 * 32 * 64 * 64 * 4B = 32 MB
__device__ float g_state[(size_t)BH * NC * DD * DD];

// ---------------------------------------------------------------------------
// helpers
// ---------------------------------------------------------------------------
__device__ __forceinline__ uint32_t smem_u32(const void* p) {
    uint32_t a;
    asm("{ .reg .u64 t; cvta.to.shared.u64 t, %1; cvt.u32.u64 %0, t; }" : "=r"(a) : "l"(p));
    return a;
}
__device__ __forceinline__ void ldsm4(uint32_t addr, uint32_t r[4]) {
    asm volatile("ldmatrix.sync.aligned.m8n8.x4.shared.b16 {%0,%1,%2,%3}, [%4];"
                 : "=r"(r[0]), "=r"(r[1]), "=r"(r[2]), "=r"(r[3]) : "r"(addr));
}
__device__ __forceinline__ void ldsm4t(uint32_t addr, uint32_t r[4]) {
    asm volatile("ldmatrix.sync.aligned.m8n8.x4.trans.shared.b16 {%0,%1,%2,%3}, [%4];"
                 : "=r"(r[0]), "=r"(r[1]), "=r"(r[2]), "=r"(r[3]) : "r"(addr));
}
__device__ __forceinline__ void mma16816(float c[4], const uint32_t a[4], uint32_t b0, uint32_t b1) {
    asm volatile(
        "mma.sync.aligned.m16n8k16.row.col.f32.bf16.bf16.f32 "
        "{%0,%1,%2,%3}, {%4,%5,%6,%7}, {%8,%9}, {%0,%1,%2,%3};"
        : "+f"(c[0]), "+f"(c[1]), "+f"(c[2]), "+f"(c[3])
        : "r"(a[0]), "r"(a[1]), "r"(a[2]), "r"(a[3]), "r"(b0), "r"(b1));
}
__device__ __forceinline__ void split_bf(float x, __nv_bfloat16& h, __nv_bfloat16& l) {
    h = __float2bfloat16(x);
    l = __float2bfloat16(x - __bfloat162float(h));
}
__device__ __forceinline__ uint32_t pack2(__nv_bfloat16 a, __nv_bfloat16 b) {
    __nv_bfloat162 v = __halves2bfloat162(a, b);
    return *reinterpret_cast<uint32_t*>(&v);
}
__device__ __forceinline__ void split4(float4 f, uint2& hi, uint2& lo) {
    __nv_bfloat16 h0, l0, h1, l1, h2, l2, h3, l3;
    split_bf(f.x, h0, l0); split_bf(f.y, h1, l1);
    split_bf(f.z, h2, l2); split_bf(f.w, h3, l3);
    hi = make_uint2(pack2(h0, h1), pack2(h2, h3));
    lo = make_uint2(pack2(l0, l1), pack2(l2, l3));
}

// ---------------------------------------------------------------------------
// Kernel 1 (fused kv + prefix): one CTA per (bh, e-half). Walks all 32 chunks
// sequentially, MMA-accumulating K^T V into fp32 register accumulators and
// snapshotting the EXCLUSIVE prefix state to gmem before each chunk.
// Double-buffered smem staging.
// ---------------------------------------------------------------------------
#define S_KH(b) ((b)*TILE_B)                    // 0, 9216
#define S_KL(b) (2*TILE_B + (b)*TILE_B)         // 18432, 27648
#define S_VH(b) (4*TILE_B + (b)*(DD*PIT2*2))    // 36864, +5120
#define S_VL(b) (4*TILE_B + 2*(DD*PIT2*2) + (b)*(DD*PIT2*2))
#define S_SMEM  (4*TILE_B + 4*(DD*PIT2*2))      // 57344

__global__ __launch_bounds__(128) void state_kernel(const float* __restrict__ kg,
                                                    const float* __restrict__ vg) {
    extern __shared__ char sm[];
    const uint32_t sb = smem_u32(sm);
    const int tid = threadIdx.x, w = tid >> 5, l = tid & 31;
    const int h = blockIdx.x;      // e-half: 0 or 1
    const int bh = blockIdx.y;

    const float* kp0 = kg + (size_t)bh * TT * DD;
    const float* vp0 = vg + (size_t)bh * TT * DD + h * 32;

    // staging lambda-ish (macro via inline code): chunk c into buffer buf
#define STAGE(cc, buf) do {                                                         \
    const float* kp = kp0 + (size_t)(cc) * CH * DD;                                 \
    const float* vp = vp0 + (size_t)(cc) * CH * DD;                                 \
    _Pragma("unroll")                                                               \
    for (int it = 0; it < 8; it++) {                                                \
        int idx = tid + it * 128;                                                   \
        int j = idx >> 4, d0 = (idx & 15) * 4;                                      \
        uint2 hi, lo;                                                               \
        split4(*(const float4*)(kp + (size_t)j * DD + d0), hi, lo);                 \
        *(uint2*)(sm + S_KH(buf) + (j * PIT + d0) * 2) = hi;                        \
        *(uint2*)(sm + S_KL(buf) + (j * PIT + d0) * 2) = lo;                        \
    }                                                                               \
    _Pragma("unroll")                                                               \
    for (int it = 0; it < 4; it++) {                                                \
        int idx = tid + it * 128;                                                   \
        int j = idx >> 3, e0 = (idx & 7) * 4;                                       \
        uint2 hi, lo;                                                               \
        split4(*(const float4*)(vp + (size_t)j * DD + e0), hi, lo);                 \
        *(uint2*)(sm + S_VH(buf) + (j * PIT2 + e0) * 2) = hi;                       \
        *(uint2*)(sm + S_VL(buf) + (j * PIT2 + e0) * 2) = lo;                       \
    }                                                                               \
} while (0)

    const int m0 = (w & 1) * 32;          // d-half within 64
    const int n0 = (w >> 1) * 16;         // e 16-block within the 32-col half
    const int gid = l >> 2, tig = l & 3;
    const int eBase = h * 32 + n0;

    // trans-A (K^T): rows = k(j), cols = m(d)
    const uint32_t aOff = (((l & 7) + ((l >> 4) & 1) * 8) * PIT + m0 + (l & 8)) * 2;
    // trans-B (V^T): rows = k(j), cols = n(e), 16 cols per warp
    const uint32_t bOff = (((l & 7) + (l & 8)) * PIT2 + n0 + ((l >> 4) & 1) * 8) * 2;

    float acc[2][2][4] = {};   // [m16 blk][n8 blk][frag]

    STAGE(0, 0);
    __syncthreads();

    for (int c = 0; c < NC; c++) {
        const int buf = c & 1;

        // prefetch next chunk into the other buffer (overlaps with MMA below)
        if (c + 1 < NC) STAGE(c + 1, buf ^ 1);

        // snapshot EXCLUSIVE prefix (state before chunk c) from registers
        {
            float* outp = g_state + ((size_t)(bh * NC + c)) * (DD * DD);
#pragma unroll
            for (int mi = 0; mi < 2; mi++)
#pragma unroll
                for (int ni = 0; ni < 2; ni++)
#pragma unroll
                    for (int half = 0; half < 2; half++) {
                        int d = m0 + mi * 16 + gid + half * 8;
                        int e = eBase + ni * 8 + 2 * tig;
                        *(float2*)(outp + (size_t)d * DD + e) =
                            make_float2(acc[mi][ni][2 * half], acc[mi][ni][2 * half + 1]);
                    }
        }

        // accumulate chunk c: acc += K_c^T V_c (3 split passes)
        {
            const uint32_t aS[3] = {(uint32_t)S_KH(buf), (uint32_t)S_KH(buf), (uint32_t)S_KL(buf)};
            const uint32_t bS[3] = {(uint32_t)S_VH(buf), (uint32_t)S_VL(buf), (uint32_t)S_VH(buf)};
#pragma unroll
            for (int p = 0; p < 3; p++) {
                const uint32_t aB = sb + aS[p] + aOff, bB = sb + bS[p] + bOff;
#pragma unroll
                for (int ks = 0; ks < 4; ks++) {
                    uint32_t a0[4], a1[4], b[4];
                    ldsm4t(aB + ks * 16 * PIT * 2, a0);
                    ldsm4t(aB + ks * 16 * PIT * 2 + 32, a1);   // d +16
                    ldsm4t(bB + ks * 16 * PIT2 * 2, b);
                    mma16816(acc[0][0], a0, b[0], b[1]);
                    mma16816(acc[0][1], a0, b[2], b[3]);
                    mma16816(acc[1][0], a1, b[0], b[1]);
                    mma16816(acc[1][1], a1, b[2], b[3]);
                }
            }
        }
        __syncthreads();
    }
#undef STAGE
}

// ---------------------------------------------------------------------------
// Kernel 3 (unchanged, R4-proven): P = tril(Q K^T); O = Q S + P V.
// ---------------------------------------------------------------------------
#define K3_QH 0
#define K3_QL (1*TILE_B)
#define K3_KH (2*TILE_B)
#define K3_KL (3*TILE_B)
#define K3_VH (4*TILE_B)
#define K3_VL (5*TILE_B)
#define K3_SH (6*TILE_B)
#define K3_SL (7*TILE_B)
#define K3_SMEM (8*TILE_B)

__global__ __launch_bounds__(128) void out_kernel(const float* __restrict__ qg,
                                                  const float* __restrict__ kg,
                                                  const float* __restrict__ vg,
                                                  float* __restrict__ og) {
    extern __shared__ char sm[];
    const uint32_t sb = smem_u32(sm);
    const int tid = threadIdx.x, w = tid >> 5, l = tid & 31;
    const int c = blockIdx.x, bh = blockIdx.y;

    const float* qp = qg + ((size_t)bh * TT + (size_t)c * CH) * DD;
    const float* kp = kg + ((size_t)bh * TT + (size_t)c * CH) * DD;
    const float* vp = vg + ((size_t)bh * TT + (size_t)c * CH) * DD;
    const float* sp = g_state + ((size_t)(bh * NC + c)) * (DD * DD);

#pragma unroll
    for (int it = 0; it < 8; it++) {
        int idx = tid + it * 128;
        int r = idx >> 4, d0 = (idx & 15) * 4;
        const uint32_t so = (r * PIT + d0) * 2;
        uint2 hi, lo;
        split4(*(const float4*)(qp + (size_t)r * DD + d0), hi, lo);
        *(uint2*)(sm + K3_QH + so) = hi;  *(uint2*)(sm + K3_QL + so) = lo;
        split4(*(const float4*)(kp + (size_t)r * DD + d0), hi, lo);
        *(uint2*)(sm + K3_KH + so) = hi;  *(uint2*)(sm + K3_KL + so) = lo;
        split4(*(const float4*)(vp + (size_t)r * DD + d0), hi, lo);
        *(uint2*)(sm + K3_VH + so) = hi;  *(uint2*)(sm + K3_VL + so) = lo;
        split4(*(const float4*)(sp + (size_t)r * DD + d0), hi, lo);
        *(uint2*)(sm + K3_SH + so) = hi;  *(uint2*)(sm + K3_SL + so) = lo;
    }
    __syncthreads();

    const int m0 = w * 16;
    const int gid = l >> 2, tig = l & 3;
    const uint32_t aOffN = ((m0 + (l & 15)) * PIT + ((l >> 4) << 3)) * 2;
    const uint32_t bOffN = (((l & 7) + ((l & 16) >> 1)) * PIT + ((l >> 3) & 1) * 8) * 2;
    const uint32_t bOffT = (((l & 7) + (l & 8)) * PIT + ((l >> 4) & 1) * 8) * 2;

    // ---- P = Q K^T (causal: only n-blocks j <= 16(w+1)) ----
    float accP[8][4] = {};
    {
        const uint32_t aS[3] = {K3_QH, K3_QH, K3_QL};
        const uint32_t bS[3] = {K3_KH, K3_KL, K3_KH};
#pragma unroll
        for (int p = 0; p < 3; p++) {
            const uint32_t aB = sb + aS[p] + aOffN, bB = sb + bS[p] + bOffN;
#pragma unroll
            for (int ks = 0; ks < 4; ks++) {
                uint32_t a[4];
                ldsm4(aB + ks * 32, a);
#pragma unroll
                for (int nb = 0; nb < 4; nb++)
                    if (nb <= w) {
                        uint32_t b[4];
                        ldsm4(bB + nb * 16 * PIT * 2 + ks * 32, b);
                        mma16816(accP[2 * nb],     a, b[0], b[1]);
                        mma16816(accP[2 * nb + 1], a, b[2], b[3]);
                    }
            }
        }
    }

    // ---- mask + in-register split to A-operand fragments ----
    uint32_t aPh[4][4], aPl[4][4];
    const int i0 = m0 + gid;
#pragma unroll
    for (int nb = 0; nb < 4; nb++)
        if (nb <= w) {
#pragma unroll
            for (int s2 = 0; s2 < 2; s2++) {
                const int j0 = 16 * nb + 8 * s2 + 2 * tig;
                float c0 = (j0     <= i0)     ? accP[2 * nb + s2][0] : 0.f;
                float c1 = (j0 + 1 <= i0)     ? accP[2 * nb + s2][1] : 0.f;
                float c2 = (j0     <= i0 + 8) ? accP[2 * nb + s2][2] : 0.f;
                float c3 = (j0 + 1 <= i0 + 8) ? accP[2 * nb + s2][3] : 0.f;
                __nv_bfloat16 h0, l0, h1, l1, h2, l2, h3, l3;
                split_bf(c0, h0, l0); split_bf(c1, h1, l1);
                split_bf(c2, h2, l2); split_bf(c3, h3, l3);
                aPh[nb][2 * s2]     = pack2(h0, h1);
                aPh[nb][2 * s2 + 1] = pack2(h2, h3);
                aPl[nb][2 * s2]     = pack2(l0, l1);
                aPl[nb][2 * s2 + 1] = pack2(l2, l3);
            }
        }

    // ---- O1 = Q @ S (B = S^T via trans loads of S[d][e]) ----
    float accO[8][4] = {};
    {
        const uint32_t aS[3] = {K3_QH, K3_QH, K3_QL};
        const uint32_t bS[3] = {K3_SH, K3_SL, K3_SH};
#pragma unroll
        for (int p = 0; p < 3; p++) {
            const uint32_t aB = sb + aS[p] + aOffN, bB = sb + bS[p] + bOffT;
#pragma unroll
            for (int ks = 0; ks < 4; ks++) {
                uint32_t a[4];
                ldsm4(aB + ks * 32, a);
#pragma unroll
                for (int nb = 0; nb < 4; nb++) {
                    uint32_t b[4];
                    ldsm4t(bB + ks * 16 * PIT * 2 + nb * 32, b);
                    mma16816(accO[2 * nb],     a, b[0], b[1]);
                    mma16816(accO[2 * nb + 1], a, b[2], b[3]);
                }
            }
        }
    }

    // ---- O2 += P @ V (A = register P, B = V^T trans; causal k-blocks only) ----
    {
#pragma unroll
        for (int p = 0; p < 3; p++) {
            const uint32_t bB = sb + (p == 1 ? K3_VL : K3_VH) + bOffT;
#pragma unroll
            for (int kb = 0; kb < 4; kb++)
                if (kb <= w) {
                    const uint32_t (&a)[4] = (p < 2) ? aPh[kb] : aPl[kb];
#pragma unroll
                    for (int nb = 0; nb < 4; nb++) {
                        uint32_t b[4];
                        ldsm4t(bB + kb * 16 * PIT * 2 + nb * 32, b);
                        mma16816(accO[2 * nb],     a, b[0], b[1]);
                        mma16816(accO[2 * nb + 1], a, b[2], b[3]);
                    }
                }
        }
    }

    // ---- store O ----
    float* op = og + ((size_t)bh * TT + (size_t)c * CH) * DD;
#pragma unroll
    for (int nb8 = 0; nb8 < 8; nb8++) {
        const int e = 8 * nb8 + 2 * tig;
        *(float2*)(op + (size_t)i0 * DD + e)       = make_float2(accO[nb8][0], accO[nb8][1]);
        *(float2*)(op + (size_t)(i0 + 8) * DD + e) = make_float2(accO[nb8][2], accO[nb8][3]);
    }
}

// ---------------------------------------------------------------------------
extern "C" void kernel_launch(void* const* d_in, const int* in_sizes, int n_in,
                              void* d_out, int out_size) {
    const float* q = (const float*)d_in[0];
    const float* k = (const float*)d_in[1];
    const float* v = (const float*)d_in[2];
    float* o = (float*)d_out;

    cudaFuncSetAttribute(state_kernel, cudaFuncAttributeMaxDynamicSharedMemorySize, S_SMEM);
    cudaFuncSetAttribute(out_kernel, cudaFuncAttributeMaxDynamicSharedMemorySize, K3_SMEM);

    state_kernel<<<dim3(2, BH), 128, S_SMEM>>>(k, v);
    out_kernel<<<dim3(NC, BH), 128, K3_SMEM>>>(q, k, v, o);
}

// round 8
// speedup vs baseline: 1.2641x; 1.2641x over previous
#include <cuda_runtime.h>
#include <cuda_bf16.h>
#include <cstdint>

#define TT   2048
#define DD   64
#define CH   64
#define NC   (TT/CH)    // 32 chunks
#define BH   64         // B*H
#define PIT  72         // smem pitch in bf16 elements (144B rows, ldmatrix conflict-free)
#define TILE_B (DD*PIT*2)  // 9216 bytes per 64x64 bf16 tile

// Exclusive-prefix KV states, fp32: 64 * 32 * 64 * 64 * 4B = 32 MB
__device__ float g_state[(size_t)BH * NC * DD * DD];

// ---------------------------------------------------------------------------
// helpers
// ---------------------------------------------------------------------------
__device__ __forceinline__ uint32_t smem_u32(const void* p) {
    uint32_t a;
    asm("{ .reg .u64 t; cvta.to.shared.u64 t, %1; cvt.u32.u64 %0, t; }" : "=r"(a) : "l"(p));
    return a;
}
__device__ __forceinline__ void ldsm4(uint32_t addr, uint32_t r[4]) {
    asm volatile("ldmatrix.sync.aligned.m8n8.x4.shared.b16 {%0,%1,%2,%3}, [%4];"
                 : "=r"(r[0]), "=r"(r[1]), "=r"(r[2]), "=r"(r[3]) : "r"(addr));
}
__device__ __forceinline__ void ldsm4t(uint32_t addr, uint32_t r[4]) {
    asm volatile("ldmatrix.sync.aligned.m8n8.x4.trans.shared.b16 {%0,%1,%2,%3}, [%4];"
                 : "=r"(r[0]), "=r"(r[1]), "=r"(r[2]), "=r"(r[3]) : "r"(addr));
}
__device__ __forceinline__ void mma16816(float c[4], const uint32_t a[4], uint32_t b0, uint32_t b1) {
    asm volatile(
        "mma.sync.aligned.m16n8k16.row.col.f32.bf16.bf16.f32 "
        "{%0,%1,%2,%3}, {%4,%5,%6,%7}, {%8,%9}, {%0,%1,%2,%3};"
        : "+f"(c[0]), "+f"(c[1]), "+f"(c[2]), "+f"(c[3])
        : "r"(a[0]), "r"(a[1]), "r"(a[2]), "r"(a[3]), "r"(b0), "r"(b1));
}
__device__ __forceinline__ void split_bf(float x, __nv_bfloat16& h, __nv_bfloat16& l) {
    h = __float2bfloat16(x);
    l = __float2bfloat16(x - __bfloat162float(h));
}
__device__ __forceinline__ uint32_t pack2(__nv_bfloat16 a, __nv_bfloat16 b) {
    __nv_bfloat162 v = __halves2bfloat162(a, b);
    return *reinterpret_cast<uint32_t*>(&v);
}
__device__ __forceinline__ void split4(float4 f, uint2& hi, uint2& lo) {
    __nv_bfloat16 h0, l0, h1, l1, h2, l2, h3, l3;
    split_bf(f.x, h0, l0); split_bf(f.y, h1, l1);
    split_bf(f.z, h2, l2); split_bf(f.w, h3, l3);
    hi = make_uint2(pack2(h0, h1), pack2(h2, h3));
    lo = make_uint2(pack2(l0, l1), pack2(l2, l3));
}

// ---------------------------------------------------------------------------
// Kernel 1: KV_c = K_c^T V_c (R6-proven, unchanged)
// ---------------------------------------------------------------------------
#define K1_KH 0
#define K1_KL (1*TILE_B)
#define K1_VH (2*TILE_B)
#define K1_VL (3*TILE_B)
#define K1_SMEM (4*TILE_B)

__global__ __launch_bounds__(128) void kv_kernel(const float* __restrict__ kg,
                                                 const float* __restrict__ vg) {
    extern __shared__ char sm[];
    const uint32_t sb = smem_u32(sm);
    const int tid = threadIdx.x, w = tid >> 5, l = tid & 31;
    const int c = blockIdx.x, bh = blockIdx.y;

    const float* kp = kg + ((size_t)bh * TT + (size_t)c * CH) * DD;
    const float* vp = vg + ((size_t)bh * TT + (size_t)c * CH) * DD;

#pragma unroll
    for (int it = 0; it < 8; it++) {
        int idx = tid + it * 128;
        int j = idx >> 4, d0 = (idx & 15) * 4;
        uint2 hi, lo;
        split4(*(const float4*)(kp + (size_t)j * DD + d0), hi, lo);
        *(uint2*)(sm + K1_KH + (j * PIT + d0) * 2) = hi;
        *(uint2*)(sm + K1_KL + (j * PIT + d0) * 2) = lo;
        split4(*(const float4*)(vp + (size_t)j * DD + d0), hi, lo);
        *(uint2*)(sm + K1_VH + (j * PIT + d0) * 2) = hi;
        *(uint2*)(sm + K1_VL + (j * PIT + d0) * 2) = lo;
    }
    __syncthreads();

    const int m0 = (w & 1) * 32, n0 = (w >> 1) * 32;
    const uint32_t aOff = (((l & 7) + ((l >> 4) & 1) * 8) * PIT + m0 + (l & 8)) * 2;
    const uint32_t bOff = (((l & 7) + (l & 8)) * PIT + n0 + ((l >> 4) & 1) * 8) * 2;

    float acc[2][4][4] = {};
    const uint32_t aSel[3] = {K1_KH, K1_KH, K1_KL};
    const uint32_t bSel[3] = {K1_VH, K1_VL, K1_VH};
#pragma unroll
    for (int p = 0; p < 3; p++) {
        const uint32_t aB = sb + aSel[p] + aOff, bB = sb + bSel[p] + bOff;
#pragma unroll
        for (int ks = 0; ks < 4; ks++) {
            const uint32_t ko = ks * 16 * PIT * 2;
            uint32_t a0[4], a1[4], b0[4], b1[4];
            ldsm4t(aB + ko, a0);
            ldsm4t(aB + ko + 32, a1);
            ldsm4t(bB + ko, b0);
            ldsm4t(bB + ko + 32, b1);
            mma16816(acc[0][0], a0, b0[0], b0[1]); mma16816(acc[0][1], a0, b0[2], b0[3]);
            mma16816(acc[0][2], a0, b1[0], b1[1]); mma16816(acc[0][3], a0, b1[2], b1[3]);
            mma16816(acc[1][0], a1, b0[0], b0[1]); mma16816(acc[1][1], a1, b0[2], b0[3]);
            mma16816(acc[1][2], a1, b1[0], b1[1]); mma16816(acc[1][3], a1, b1[2], b1[3]);
        }
    }

    float* outp = g_state + ((size_t)(bh * NC + c)) * (DD * DD);
#pragma unroll
    for (int mi = 0; mi < 2; mi++)
#pragma unroll
        for (int ni = 0; ni < 4; ni++)
#pragma unroll
            for (int half = 0; half < 2; half++) {
                int d = m0 + mi * 16 + (l >> 2) + half * 8;
                int e = n0 + ni * 8 + 2 * (l & 3);
                *(float2*)(outp + (size_t)d * DD + e) =
                    make_float2(acc[mi][ni][2 * half], acc[mi][ni][2 * half + 1]);
            }
}

// ---------------------------------------------------------------------------
// Kernel 2: exclusive prefix — batched loads then register prefix.
// ---------------------------------------------------------------------------
__global__ __launch_bounds__(256) void prefix_kernel() {
    const int e2 = blockIdx.x * 256 + threadIdx.x;   // pair index 0..2047
    const int bh = blockIdx.y;
    const size_t stride = DD * DD;
    float* base = g_state + (size_t)bh * NC * stride + 2 * (size_t)e2;

    float2 vals[NC];
#pragma unroll
    for (int c = 0; c < NC; c++)
        vals[c] = *(const float2*)(base + (size_t)c * stride);

    float2 run = make_float2(0.f, 0.f);
#pragma unroll
    for (int c = 0; c < NC; c++) {
        float2 t = vals[c];
        *(float2*)(base + (size_t)c * stride) = run;
        run.x += t.x;
        run.y += t.y;
    }
}

// ---------------------------------------------------------------------------
// Kernel 3: P = tril(Q K^T); O = Q S + P V.
// smem 6 tiles: S overlays the K tiles after the P-pass (K dead by then).
// S prefetched to registers during staging (deep MLP), split after P.
// ---------------------------------------------------------------------------
#define K3_QH 0
#define K3_QL (1*TILE_B)
#define K3_KH 
#define K3_KSH (2*TILE_B)   // K during P-pass, then S
#define K3_KSL (3*TILE_B)
#define K3_VH (4*TILE_B)
#define K3_VL (5*TILE_B)
#define K3_SMEM (6*TILE_B)  // 55296 B

__global__ __launch_bounds__(128) void out_kernel(const float* __restrict__ qg,
                                                  const float* __restrict__ kg,
                                                  const float* __restrict__ vg,
                                                  float* __restrict__ og) {
    extern __shared__ char sm[];
    const uint32_t sb = smem_u32(sm);
    const int tid = threadIdx.x, w = tid >> 5, l = tid & 31;
    const int c = blockIdx.x, bh = blockIdx.y;

    const float* qp = qg + ((size_t)bh * TT + (size_t)c * CH) * DD;
    const float* kp = kg + ((size_t)bh * TT + (size_t)c * CH) * DD;
    const float* vp = vg + ((size_t)bh * TT + (size_t)c * CH) * DD;
    const float* sp = g_state + ((size_t)(bh * NC + c)) * (DD * DD);

    // prefetch S into registers (8 float4 per thread; LDGs issue early)
    float4 sReg[8];
#pragma unroll
    for (int it = 0; it < 8; it++) {
        int idx = tid + it * 128;
        int r = idx >> 4, d0 = (idx & 15) * 4;
        sReg[it] = *(const float4*)(sp + (size_t)r * DD + d0);
    }

#pragma unroll
    for (int it = 0; it < 8; it++) {
        int idx = tid + it * 128;
        int r = idx >> 4, d0 = (idx & 15) * 4;
        const uint32_t so = (r * PIT + d0) * 2;
        uint2 hi, lo;
        split4(*(const float4*)(qp + (size_t)r * DD + d0), hi, lo);
        *(uint2*)(sm + K3_QH + so) = hi;  *(uint2*)(sm + K3_QL + so) = lo;
        split4(*(const float4*)(kp + (size_t)r * DD + d0), hi, lo);
        *(uint2*)(sm + K3_KSH + so) = hi; *(uint2*)(sm + K3_KSL + so) = lo;
        split4(*(const float4*)(vp + (size_t)r * DD + d0), hi, lo);
        *(uint2*)(sm + K3_VH + so) = hi;  *(uint2*)(sm + K3_VL + so) = lo;
    }
    __syncthreads();

    const int m0 = w * 16;
    const int gid = l >> 2, tig = l & 3;
    const int i0 = m0 + gid;
    const uint32_t aOffN = ((m0 + (l & 15)) * PIT + ((l >> 4) << 3)) * 2;
    const uint32_t bOffN = (((l & 7) + ((l & 16) >> 1)) * PIT + ((l >> 3) & 1) * 8) * 2;
    const uint32_t bOffT = (((l & 7) + (l & 8)) * PIT + ((l >> 4) & 1) * 8) * 2;

    // ---- P = Q K^T (causal: only n-blocks j <= 16(w+1)) ----
    float accP[8][4] = {};
    {
        const uint32_t aS[3] = {K3_QH, K3_QH, K3_QL};
        const uint32_t bS[3] = {K3_KSH, K3_KSL, K3_KSH};
#pragma unroll
        for (int p = 0; p < 3; p++) {
            const uint32_t aB = sb + aS[p] + aOffN, bB = sb + bS[p] + bOffN;
#pragma unroll
            for (int ks = 0; ks < 4; ks++) {
                uint32_t a[4];
                ldsm4(aB + ks * 32, a);
#pragma unroll
                for (int nb = 0; nb < 4; nb++)
                    if (nb <= w) {
                        uint32_t b[4];
                        ldsm4(bB + nb * 16 * PIT * 2 + ks * 32, b);
                        mma16816(accP[2 * nb],     a, b[0], b[1]);
                        mma16816(accP[2 * nb + 1], a, b[2], b[3]);
                    }
            }
        }
    }

    // ---- mask + in-register split of P to A-operand fragments ----
    uint32_t aPh[4][4], aPl[4][4];
#pragma unroll
    for (int nb = 0; nb < 4; nb++)
        if (nb <= w) {
#pragma unroll
            for (int s2 = 0; s2 < 2; s2++) {
                const int j0 = 16 * nb + 8 * s2 + 2 * tig;
                float c0 = (j0     <= i0)     ? accP[2 * nb + s2][0] : 0.f;
                float c1 = (j0 + 1 <= i0)     ? accP[2 * nb + s2][1] : 0.f;
                float c2 = (j0     <= i0 + 8) ? accP[2 * nb + s2][2] : 0.f;
                float c3 = (j0 + 1 <= i0 + 8) ? accP[2 * nb + s2][3] : 0.f;
                __nv_bfloat16 h0, l0, h1, l1, h2, l2, h3, l3;
                split_bf(c0, h0, l0); split_bf(c1, h1, l1);
                split_bf(c2, h2, l2); split_bf(c3, h3, l3);
                aPh[nb][2 * s2]     = pack2(h0, h1);
                aPh[nb][2 * s2 + 1] = pack2(h2, h3);
                aPl[nb][2 * s2]     = pack2(l0, l1);
                aPl[nb][2 * s2 + 1] = pack2(l2, l3);
            }
        }

    // ---- overlay: K tiles are dead; write S (from registers) into them ----
    __syncthreads();   // all warps done reading K
#pragma unroll
    for (int it = 0; it < 8; it++) {
        int idx = tid + it * 128;
        int r = idx >> 4, d0 = (idx & 15) * 4;
        const uint32_t so = (r * PIT + d0) * 2;
        uint2 hi, lo;
        split4(sReg[it], hi, lo);
        *(uint2*)(sm + K3_KSH + so) = hi;
        *(uint2*)(sm + K3_KSL + so) = lo;
    }
    __syncthreads();

    // ---- O1 = Q @ S (B = S^T via trans loads of S[d][e]) ----
    float accO[8][4] = {};
    {
        const uint32_t aS[3] = {K3_QH, K3_QH, K3_QL};
        const uint32_t bS[3] = {K3_KSH, K3_KSL, K3_KSH};
#pragma unroll
        for (int p = 0; p < 3; p++) {
            const uint32_t aB = sb + aS[p] + aOffN, bB = sb + bS[p] + bOffT;
#pragma unroll
            for (int ks = 0; ks < 4; ks++) {
                uint32_t a[4];
                ldsm4(aB + ks * 32, a);
#pragma unroll
                for (int nb = 0; nb < 4; nb++) {
                    uint32_t b[4];
                    ldsm4t(bB + ks * 16 * PIT * 2 + nb * 32, b);
                    mma16816(accO[2 * nb],     a, b[0], b[1]);
                    mma16816(accO[2 * nb + 1], a, b[2], b[3]);
                }
            }
        }
    }

    // ---- O2 += P @ V (A = register P, B = V^T trans; causal k-blocks only) ----
    {
#pragma unroll
        for (int p = 0; p < 3; p++) {
            const uint32_t bB = sb + (p == 1 ? K3_VL : K3_VH) + bOffT;
#pragma unroll
            for (int kb = 0; kb < 4; kb++)
                if (kb <= w) {
                    const uint32_t (&a)[4] = (p < 2) ? aPh[kb] : aPl[kb];
#pragma unroll
                    for (int nb = 0; nb < 4; nb++) {
                        uint32_t b[4];
                        ldsm4t(bB + kb * 16 * PIT * 2 + nb * 32, b);
                        mma16816(accO[2 * nb],     a, b[0], b[1]);
                        mma16816(accO[2 * nb + 1], a, b[2], b[3]);
                    }
                }
        }
    }

    // ---- store O ----
    float* op = og + ((size_t)bh * TT + (size_t)c * CH) * DD;
#pragma unroll
    for (int nb8 = 0; nb8 < 8; nb8++) {
        const int e = 8 * nb8 + 2 * tig;
        *(float2*)(op + (size_t)i0 * DD + e)       = make_float2(accO[nb8][0], accO[nb8][1]);
        *(float2*)(op + (size_t)(i0 + 8) * DD + e) = make_float2(accO[nb8][2], accO[nb8][3]);
    }
}

// ---------------------------------------------------------------------------
extern "C" void kernel_launch(void* const* d_in, const int* in_sizes, int n_in,
                              void* d_out, int out_size) {
    const float* q = (const float*)d_in[0];
    const float* k = (const float*)d_in[1];
    const float* v = (const float*)d_in[2];
    float* o = (float*)d_out;

    cudaFuncSetAttribute(kv_kernel, cudaFuncAttributeMaxDynamicSharedMemorySize, K1_SMEM);
    cudaFuncSetAttribute(out_kernel, cudaFuncAttributeMaxDynamicSharedMemorySize, K3_SMEM);
    cudaFuncSetAttribute(kv_kernel, cudaFuncAttributePreferredSharedMemoryCarveout, 100);
    cudaFuncSetAttribute(out_kernel, cudaFuncAttributePreferredSharedMemoryCarveout, 100);

    dim3 grid(NC, BH);
    kv_kernel<<<grid, 128, K1_SMEM>>>(k, v);
    prefix_kernel<<<dim3((DD * DD / 2) / 256, BH), 256>>>();
    out_kernel<<<grid, 128, K3_SMEM>>>(q, k, v, o);
}

// round 9
// speedup vs baseline: 1.3250x; 1.0482x over previous
#include <cuda_runtime.h>
#include <cuda_bf16.h>
#include <cstdint>

#define TT   2048
#define DD   64
#define CH   64
#define NC   (TT/CH)    // 32 chunks
#define BH   64         // B*H
#define PIT  72         // smem pitch in bf16 elements (144B rows, ldmatrix conflict-free)
#define TILE_B (DD*PIT*2)  // 9216 bytes per 64x64 bf16 tile

// Raw per-chunk KV states (kv_kernel -> prefix_kernel), fp32: 32 MB
__device__ float g_state[(size_t)BH * NC * DD * DD];
// Exclusive-prefix states, pre-split bf16 planes (prefix_kernel -> out_kernel): 16 MB each
__device__ uint32_t g_sh[(size_t)BH * NC * DD * DD / 2];
__device__ uint32_t g_sl[(size_t)BH * NC * DD * DD / 2];

// ---------------------------------------------------------------------------
// helpers
// ---------------------------------------------------------------------------
__device__ __forceinline__ uint32_t smem_u32(const void* p) {
    uint32_t a;
    asm("{ .reg .u64 t; cvta.to.shared.u64 t, %1; cvt.u32.u64 %0, t; }" : "=r"(a) : "l"(p));
    return a;
}
__device__ __forceinline__ void ldsm4(uint32_t addr, uint32_t r[4]) {
    asm volatile("ldmatrix.sync.aligned.m8n8.x4.shared.b16 {%0,%1,%2,%3}, [%4];"
                 : "=r"(r[0]), "=r"(r[1]), "=r"(r[2]), "=r"(r[3]) : "r"(addr));
}
__device__ __forceinline__ void ldsm4t(uint32_t addr, uint32_t r[4]) {
    asm volatile("ldmatrix.sync.aligned.m8n8.x4.trans.shared.b16 {%0,%1,%2,%3}, [%4];"
                 : "=r"(r[0]), "=r"(r[1]), "=r"(r[2]), "=r"(r[3]) : "r"(addr));
}
__device__ __forceinline__ void mma16816(float c[4], const uint32_t a[4], uint32_t b0, uint32_t b1) {
    asm volatile(
        "mma.sync.aligned.m16n8k16.row.col.f32.bf16.bf16.f32 "
        "{%0,%1,%2,%3}, {%4,%5,%6,%7}, {%8,%9}, {%0,%1,%2,%3};"
        : "+f"(c[0]), "+f"(c[1]), "+f"(c[2]), "+f"(c[3])
        : "r"(a[0]), "r"(a[1]), "r"(a[2]), "r"(a[3]), "r"(b0), "r"(b1));
}
__device__ __forceinline__ void split_bf(float x, __nv_bfloat16& h, __nv_bfloat16& l) {
    h = __float2bfloat16(x);
    l = __float2bfloat16(x - __bfloat162float(h));
}
__device__ __forceinline__ uint32_t pack2(__nv_bfloat16 a, __nv_bfloat16 b) {
    __nv_bfloat162 v = __halves2bfloat162(a, b);
    return *reinterpret_cast<uint32_t*>(&v);
}
__device__ __forceinline__ void split4(float4 f, uint2& hi, uint2& lo) {
    __nv_bfloat16 h0, l0, h1, l1, h2, l2, h3, l3;
    split_bf(f.x, h0, l0); split_bf(f.y, h1, l1);
    split_bf(f.z, h2, l2); split_bf(f.w, h3, l3);
    hi = make_uint2(pack2(h0, h1), pack2(h2, h3));
    lo = make_uint2(pack2(l0, l1), pack2(l2, l3));
}

// ---------------------------------------------------------------------------
// Kernel 1: KV_c = K_c^T V_c (R6-proven, unchanged; default L1 carveout)
// ---------------------------------------------------------------------------
#define K1_KH 0
#define K1_KL (1*TILE_B)
#define K1_VH (2*TILE_B)
#define K1_VL (3*TILE_B)
#define K1_SMEM (4*TILE_B)

__global__ __launch_bounds__(128) void kv_kernel(const float* __restrict__ kg,
                                                 const float* __restrict__ vg) {
    extern __shared__ char sm[];
    const uint32_t sb = smem_u32(sm);
    const int tid = threadIdx.x, w = tid >> 5, l = tid & 31;
    const int c = blockIdx.x, bh = blockIdx.y;

    const float* kp = kg + ((size_t)bh * TT + (size_t)c * CH) * DD;
    const float* vp = vg + ((size_t)bh * TT + (size_t)c * CH) * DD;

#pragma unroll
    for (int it = 0; it < 8; it++) {
        int idx = tid + it * 128;
        int j = idx >> 4, d0 = (idx & 15) * 4;
        uint2 hi, lo;
        split4(*(const float4*)(kp + (size_t)j * DD + d0), hi, lo);
        *(uint2*)(sm + K1_KH + (j * PIT + d0) * 2) = hi;
        *(uint2*)(sm + K1_KL + (j * PIT + d0) * 2) = lo;
        split4(*(const float4*)(vp + (size_t)j * DD + d0), hi, lo);
        *(uint2*)(sm + K1_VH + (j * PIT + d0) * 2) = hi;
        *(uint2*)(sm + K1_VL + (j * PIT + d0) * 2) = lo;
    }
    __syncthreads();

    const int m0 = (w & 1) * 32, n0 = (w >> 1) * 32;
    const uint32_t aOff = (((l & 7) + ((l >> 4) & 1) * 8) * PIT + m0 + (l & 8)) * 2;
    const uint32_t bOff = (((l & 7) + (l & 8)) * PIT + n0 + ((l >> 4) & 1) * 8) * 2;

    float acc[2][4][4] = {};
    const uint32_t aSel[3] = {K1_KH, K1_KH, K1_KL};
    const uint32_t bSel[3] = {K1_VH, K1_VL, K1_VH};
#pragma unroll
    for (int p = 0; p < 3; p++) {
        const uint32_t aB = sb + aSel[p] + aOff, bB = sb + bSel[p] + bOff;
#pragma unroll
        for (int ks = 0; ks < 4; ks++) {
            const uint32_t ko = ks * 16 * PIT * 2;
            uint32_t a0[4], a1[4], b0[4], b1[4];
            ldsm4t(aB + ko, a0);
            ldsm4t(aB + ko + 32, a1);
            ldsm4t(bB + ko, b0);
            ldsm4t(bB + ko + 32, b1);
            mma16816(acc[0][0], a0, b0[0], b0[1]); mma16816(acc[0][1], a0, b0[2], b0[3]);
            mma16816(acc[0][2], a0, b1[0], b1[1]); mma16816(acc[0][3], a0, b1[2], b1[3]);
            mma16816(acc[1][0], a1, b0[0], b0[1]); mma16816(acc[1][1], a1, b0[2], b0[3]);
            mma16816(acc[1][2], a1, b1[0], b1[1]); mma16816(acc[1][3], a1, b1[2], b1[3]);
        }
    }

    float* outp = g_state + ((size_t)(bh * NC + c)) * (DD * DD);
#pragma unroll
    for (int mi = 0; mi < 2; mi++)
#pragma unroll
        for (int ni = 0; ni < 4; ni++)
#pragma unroll
            for (int half = 0; half < 2; half++) {
                int d = m0 + mi * 16 + (l >> 2) + half * 8;
                int e = n0 + ni * 8 + 2 * (l & 3);
                *(float2*)(outp + (size_t)d * DD + e) =
                    make_float2(acc[mi][ni][2 * half], acc[mi][ni][2 * half + 1]);
            }
}

// ---------------------------------------------------------------------------
// Kernel 2: exclusive prefix; emits PRE-SPLIT bf16 hi/lo planes.
// ---------------------------------------------------------------------------
__global__ __launch_bounds__(256) void prefix_kernel() {
    const int e2 = blockIdx.x * 256 + threadIdx.x;   // pair index 0..2047
    const int bh = blockIdx.y;
    const size_t stride = DD * DD;
    const float* base = g_state + (size_t)bh * NC * stride + 2 * (size_t)e2;
    uint32_t* bh_h = g_sh + (size_t)bh * NC * (stride / 2) + e2;
    uint32_t* bh_l = g_sl + (size_t)bh * NC * (stride / 2) + e2;

    float2 vals[NC];
#pragma unroll
    for (int c = 0; c < NC; c++)
        vals[c] = *(const float2*)(base + (size_t)c * stride);

    float2 run = make_float2(0.f, 0.f);
#pragma unroll
    for (int c = 0; c < NC; c++) {
        __nv_bfloat16 h0, l0, h1, l1;
        split_bf(run.x, h0, l0);
        split_bf(run.y, h1, l1);
        bh_h[(size_t)c * (stride / 2)] = pack2(h0, h1);
        bh_l[(size_t)c * (stride / 2)] = pack2(l0, l1);
        run.x += vals[c].x;
        run.y += vals[c].y;
    }
}

// ---------------------------------------------------------------------------
// Kernel 3 (R6 structure): P = tril(Q K^T); O = Q S + P V.
// S staged by plain copy from pre-split planes. Full-carveout smem (3 CTAs/SM).
// ---------------------------------------------------------------------------
#define K3_QH 0
#define K3_QL (1*TILE_B)
#define K3_KH (2*TILE_B)
#define K3_KL (3*TILE_B)
#define K3_VH (4*TILE_B)
#define K3_VL (5*TILE_B)
#define K3_SH (6*TILE_B)
#define K3_SL (7*TILE_B)
#define K3_SMEM (8*TILE_B)

__global__ __launch_bounds__(128) void out_kernel(const float* __restrict__ qg,
                                                  const float* __restrict__ kg,
                                                  const float* __restrict__ vg,
                                                  float* __restrict__ og) {
    extern __shared__ char sm[];
    const uint32_t sb = smem_u32(sm);
    const int tid = threadIdx.x, w = tid >> 5, l = tid & 31;
    const int c = blockIdx.x, bh = blockIdx.y;

    const float* qp = qg + ((size_t)bh * TT + (size_t)c * CH) * DD;
    const float* kp = kg + ((size_t)bh * TT + (size_t)c * CH) * DD;
    const float* vp = vg + ((size_t)bh * TT + (size_t)c * CH) * DD;
    const uint32_t* sph = g_sh + ((size_t)(bh * NC + c)) * (DD * DD / 2);
    const uint32_t* spl = g_sl + ((size_t)(bh * NC + c)) * (DD * DD / 2);

#pragma unroll
    for (int it = 0; it < 8; it++) {
        int idx = tid + it * 128;
        int r = idx >> 4, d0 = (idx & 15) * 4;
        const uint32_t so = (r * PIT + d0) * 2;
        uint2 hi, lo;
        split4(*(const float4*)(qp + (size_t)r * DD + d0), hi, lo);
        *(uint2*)(sm + K3_QH + so) = hi;  *(uint2*)(sm + K3_QL + so) = lo;
        split4(*(const float4*)(kp + (size_t)r * DD + d0), hi, lo);
        *(uint2*)(sm + K3_KH + so) = hi;  *(uint2*)(sm + K3_KL + so) = lo;
        split4(*(const float4*)(vp + (size_t)r * DD + d0), hi, lo);
        *(uint2*)(sm + K3_VH + so) = hi;  *(uint2*)(sm + K3_VL + so) = lo;
        // S: plain copy of pre-split planes (4 bf16 = uint2 per plane)
        const size_t si = ((size_t)r * DD + d0) / 2;
        *(uint2*)(sm + K3_SH + so) = *(const uint2*)(sph + si);
        *(uint2*)(sm + K3_SL + so) = *(const uint2*)(spl + si);
    }
    __syncthreads();

    const int m0 = w * 16;
    const int gid = l >> 2, tig = l & 3;
    const int i0 = m0 + gid;
    const uint32_t aOffN = ((m0 + (l & 15)) * PIT + ((l >> 4) << 3)) * 2;
    const uint32_t bOffN = (((l & 7) + ((l & 16) >> 1)) * PIT + ((l >> 3) & 1) * 8) * 2;
    const uint32_t bOffT = (((l & 7) + (l & 8)) * PIT + ((l >> 4) & 1) * 8) * 2;

    // ---- P = Q K^T (causal: only n-blocks j <= 16(w+1)) ----
    float accP[8][4] = {};
    {
        const uint32_t aS[3] = {K3_QH, K3_QH, K3_QL};
        const uint32_t bS[3] = {K3_KH, K3_KL, K3_KH};
#pragma unroll
        for (int p = 0; p < 3; p++) {
            const uint32_t aB = sb + aS[p] + aOffN, bB = sb + bS[p] + bOffN;
#pragma unroll
            for (int ks = 0; ks < 4; ks++) {
                uint32_t a[4];
                ldsm4(aB + ks * 32, a);
#pragma unroll
                for (int nb = 0; nb < 4; nb++)
                    if (nb <= w) {
                        uint32_t b[4];
                        ldsm4(bB + nb * 16 * PIT * 2 + ks * 32, b);
                        mma16816(accP[2 * nb],     a, b[0], b[1]);
                        mma16816(accP[2 * nb + 1], a, b[2], b[3]);
                    }
            }
        }
    }

    // ---- mask + in-register split to A-operand fragments ----
    uint32_t aPh[4][4], aPl[4][4];
#pragma unroll
    for (int nb = 0; nb < 4; nb++)
        if (nb <= w) {
#pragma unroll
            for (int s2 = 0; s2 < 2; s2++) {
                const int j0 = 16 * nb + 8 * s2 + 2 * tig;
                float c0 = (j0     <= i0)     ? accP[2 * nb + s2][0] : 0.f;
                float c1 = (j0 + 1 <= i0)     ? accP[2 * nb + s2][1] : 0.f;
                float c2 = (j0     <= i0 + 8) ? accP[2 * nb + s2][2] : 0.f;
                float c3 = (j0 + 1 <= i0 + 8) ? accP[2 * nb + s2][3] : 0.f;
                __nv_bfloat16 h0, l0, h1, l1, h2, l2, h3, l3;
                split_bf(c0, h0, l0); split_bf(c1, h1, l1);
                split_bf(c2, h2, l2); split_bf(c3, h3, l3);
                aPh[nb][2 * s2]     = pack2(h0, h1);
                aPh[nb][2 * s2 + 1] = pack2(h2, h3);
                aPl[nb][2 * s2]     = pack2(l0, l1);
                aPl[nb][2 * s2 + 1] = pack2(l2, l3);
            }
        }

    // ---- O1 = Q @ S (B = S^T via trans loads of S[d][e]) ----
    float accO[8][4] = {};
    {
        const uint32_t aS[3] = {K3_QH, K3_QH, K3_QL};
        const uint32_t bS[3] = {K3_SH, K3_SL, K3_SH};
#pragma unroll
        for (int p = 0; p < 3; p++) {
            const uint32_t aB = sb + aS[p] + aOffN, bB = sb + bS[p] + bOffT;
#pragma unroll
            for (int ks = 0; ks < 4; ks++) {
                uint32_t a[4];
                ldsm4(aB + ks * 32, a);
#pragma unroll
                for (int nb = 0; nb < 4; nb++) {
                    uint32_t b[4];
                    ldsm4t(bB + ks * 16 * PIT * 2 + nb * 32, b);
                    mma16816(accO[2 * nb],     a, b[0], b[1]);
                    mma16816(accO[2 * nb + 1], a, b[2], b[3]);
                }
            }
        }
    }

    // ---- O2 += P @ V (A = register P, B = V^T trans; causal k-blocks only) ----
    {
#pragma unroll
        for (int p = 0; p < 3; p++) {
            const uint32_t bB = sb + (p == 1 ? K3_VL : K3_VH) + bOffT;
#pragma unroll
            for (int kb = 0; kb < 4; kb++)
                if (kb <= w) {
                    const uint32_t (&a)[4] = (p < 2) ? aPh[kb] : aPl[kb];
#pragma unroll
                    for (int nb = 0; nb < 4; nb++) {
                        uint32_t b[4];
                        ldsm4t(bB + kb * 16 * PIT * 2 + nb * 32, b);
                        mma16816(accO[2 * nb],     a, b[0], b[1]);
                        mma16816(accO[2 * nb + 1], a, b[2], b[3]);
                    }
                }
        }
    }

    // ---- store O ----
    float* op = og + ((size_t)bh * TT + (size_t)c * CH) * DD;
#pragma unroll
    for (int nb8 = 0; nb8 < 8; nb8++) {
        const int e = 8 * nb8 + 2 * tig;
        *(float2*)(op + (size_t)i0 * DD + e)       = make_float2(accO[nb8][0], accO[nb8][1]);
        *(float2*)(op + (size_t)(i0 + 8) * DD + e) = make_float2(accO[nb8][2], accO[nb8][3]);
    }
}

// ---------------------------------------------------------------------------
extern "C" void kernel_launch(void* const* d_in, const int* in_sizes, int n_in,
                              void* d_out, int out_size) {
    const float* q = (const float*)d_in[0];
    const float* k = (const float*)d_in[1];
    const float* v = (const float*)d_in[2];
    float* o = (float*)d_out;

    cudaFuncSetAttribute(kv_kernel, cudaFuncAttributeMaxDynamicSharedMemorySize, K1_SMEM);
    cudaFuncSetAttribute(out_kernel, cudaFuncAttributeMaxDynamicSharedMemorySize, K3_SMEM);
    // Full carveout ONLY for out_kernel (3 CTAs/SM); kv keeps default L1D.
    cudaFuncSetAttribute(out_kernel, cudaFuncAttributePreferredSharedMemoryCarveout, 100);

    dim3 grid(NC, BH);
    kv_kernel<<<grid, 128, K1_SMEM>>>(k, v);
    prefix_kernel<<<dim3((DD * DD / 2) / 256, BH), 256>>>();
    out_kernel<<<grid, 128, K3_SMEM>>>(q, k, v, o);
}

// round 10
// speedup vs baseline: 1.3742x; 1.0372x over previous
#include <cuda_runtime.h>
#include <cuda_bf16.h>
#include <cstdint>

#define TT   2048
#define DD   64
#define CH   64
#define NC   (TT/CH)    // 32 chunks
#define BH   64         // B*H
#define PIT  72         // smem pitch in bf16 elements (144B rows, ldmatrix conflict-free)
#define TILE_B (DD*PIT*2)  // 9216 bytes per 64x64 bf16 tile

// Raw per-chunk KV states (kv_kernel -> prefix_kernel), fp32: 32 MB
__device__ float g_state[(size_t)BH * NC * DD * DD];
// Exclusive-prefix states, pre-split bf16 planes (prefix_kernel -> out_kernel): 16 MB each
__device__ uint32_t g_sh[(size_t)BH * NC * DD * DD / 2];
__device__ uint32_t g_sl[(size_t)BH * NC * DD * DD / 2];

// ---------------------------------------------------------------------------
// helpers
// ---------------------------------------------------------------------------
__device__ __forceinline__ uint32_t smem_u32(const void* p) {
    uint32_t a;
    asm("{ .reg .u64 t; cvta.to.shared.u64 t, %1; cvt.u32.u64 %0, t; }" : "=r"(a) : "l"(p));
    return a;
}
__device__ __forceinline__ void ldsm4(uint32_t addr, uint32_t r[4]) {
    asm volatile("ldmatrix.sync.aligned.m8n8.x4.shared.b16 {%0,%1,%2,%3}, [%4];"
                 : "=r"(r[0]), "=r"(r[1]), "=r"(r[2]), "=r"(r[3]) : "r"(addr));
}
__device__ __forceinline__ void ldsm4t(uint32_t addr, uint32_t r[4]) {
    asm volatile("ldmatrix.sync.aligned.m8n8.x4.trans.shared.b16 {%0,%1,%2,%3}, [%4];"
                 : "=r"(r[0]), "=r"(r[1]), "=r"(r[2]), "=r"(r[3]) : "r"(addr));
}
__device__ __forceinline__ void mma16816(float c[4], const uint32_t a[4], uint32_t b0, uint32_t b1) {
    asm volatile(
        "mma.sync.aligned.m16n8k16.row.col.f32.bf16.bf16.f32 "
        "{%0,%1,%2,%3}, {%4,%5,%6,%7}, {%8,%9}, {%0,%1,%2,%3};"
        : "+f"(c[0]), "+f"(c[1]), "+f"(c[2]), "+f"(c[3])
        : "r"(a[0]), "r"(a[1]), "r"(a[2]), "r"(a[3]), "r"(b0), "r"(b1));
}
__device__ __forceinline__ void split_bf(float x, __nv_bfloat16& h, __nv_bfloat16& l) {
    h = __float2bfloat16(x);
    l = __float2bfloat16(x - __bfloat162float(h));
}
__device__ __forceinline__ uint32_t pack2(__nv_bfloat16 a, __nv_bfloat16 b) {
    __nv_bfloat162 v = __halves2bfloat162(a, b);
    return *reinterpret_cast<uint32_t*>(&v);
}
__device__ __forceinline__ void split4(float4 f, uint2& hi, uint2& lo) {
    __nv_bfloat16 h0, l0, h1, l1, h2, l2, h3, l3;
    split_bf(f.x, h0, l0); split_bf(f.y, h1, l1);
    split_bf(f.z, h2, l2); split_bf(f.w, h3, l3);
    hi = make_uint2(pack2(h0, h1), pack2(h2, h3));
    lo = make_uint2(pack2(l0, l1), pack2(l2, l3));
}

// ---------------------------------------------------------------------------
// Kernel 1: KV_c = K_c^T V_c (R6-proven, unchanged; default L1 carveout)
// ---------------------------------------------------------------------------
#define K1_KH 0
#define K1_KL (1*TILE_B)
#define K1_VH (2*TILE_B)
#define K1_VL (3*TILE_B)
#define K1_SMEM (4*TILE_B)

__global__ __launch_bounds__(128) void kv_kernel(const float* __restrict__ kg,
                                                 const float* __restrict__ vg) {
    extern __shared__ char sm[];
    const uint32_t sb = smem_u32(sm);
    const int tid = threadIdx.x, w = tid >> 5, l = tid & 31;
    const int c = blockIdx.x, bh = blockIdx.y;

    const float* kp = kg + ((size_t)bh * TT + (size_t)c * CH) * DD;
    const float* vp = vg + ((size_t)bh * TT + (size_t)c * CH) * DD;

#pragma unroll
    for (int it = 0; it < 8; it++) {
        int idx = tid + it * 128;
        int j = idx >> 4, d0 = (idx & 15) * 4;
        uint2 hi, lo;
        split4(*(const float4*)(kp + (size_t)j * DD + d0), hi, lo);
        *(uint2*)(sm + K1_KH + (j * PIT + d0) * 2) = hi;
        *(uint2*)(sm + K1_KL + (j * PIT + d0) * 2) = lo;
        split4(*(const float4*)(vp + (size_t)j * DD + d0), hi, lo);
        *(uint2*)(sm + K1_VH + (j * PIT + d0) * 2) = hi;
        *(uint2*)(sm + K1_VL + (j * PIT + d0) * 2) = lo;
    }
    __syncthreads();

    const int m0 = (w & 1) * 32, n0 = (w >> 1) * 32;
    const uint32_t aOff = (((l & 7) + ((l >> 4) & 1) * 8) * PIT + m0 + (l & 8)) * 2;
    const uint32_t bOff = (((l & 7) + (l & 8)) * PIT + n0 + ((l >> 4) & 1) * 8) * 2;

    float acc[2][4][4] = {};
    const uint32_t aSel[3] = {K1_KH, K1_KH, K1_KL};
    const uint32_t bSel[3] = {K1_VH, K1_VL, K1_VH};
#pragma unroll
    for (int p = 0; p < 3; p++) {
        const uint32_t aB = sb + aSel[p] + aOff, bB = sb + bSel[p] + bOff;
#pragma unroll
        for (int ks = 0; ks < 4; ks++) {
            const uint32_t ko = ks * 16 * PIT * 2;
            uint32_t a0[4], a1[4], b0[4], b1[4];
            ldsm4t(aB + ko, a0);
            ldsm4t(aB + ko + 32, a1);
            ldsm4t(bB + ko, b0);
            ldsm4t(bB + ko + 32, b1);
            mma16816(acc[0][0], a0, b0[0], b0[1]); mma16816(acc[0][1], a0, b0[2], b0[3]);
            mma16816(acc[0][2], a0, b1[0], b1[1]); mma16816(acc[0][3], a0, b1[2], b1[3]);
            mma16816(acc[1][0], a1, b0[0], b0[1]); mma16816(acc[1][1], a1, b0[2], b0[3]);
            mma16816(acc[1][2], a1, b1[0], b1[1]); mma16816(acc[1][3], a1, b1[2], b1[3]);
        }
    }

    float* outp = g_state + ((size_t)(bh * NC + c)) * (DD * DD);
#pragma unroll
    for (int mi = 0; mi < 2; mi++)
#pragma unroll
        for (int ni = 0; ni < 4; ni++)
#pragma unroll
            for (int half = 0; half < 2; half++) {
                int d = m0 + mi * 16 + (l >> 2) + half * 8;
                int e = n0 + ni * 8 + 2 * (l & 3);
                *(float2*)(outp + (size_t)d * DD + e) =
                    make_float2(acc[mi][ni][2 * half], acc[mi][ni][2 * half + 1]);
            }
}

// ---------------------------------------------------------------------------
// Kernel 2: exclusive prefix; emits PRE-SPLIT bf16 hi/lo planes.
// ---------------------------------------------------------------------------
__global__ __launch_bounds__(256) void prefix_kernel() {
    const int e2 = blockIdx.x * 256 + threadIdx.x;   // pair index 0..2047
    const int bh = blockIdx.y;
    const size_t stride = DD * DD;
    const float* base = g_state + (size_t)bh * NC * stride + 2 * (size_t)e2;
    uint32_t* bh_h = g_sh + (size_t)bh * NC * (stride / 2) + e2;
    uint32_t* bh_l = g_sl + (size_t)bh * NC * (stride / 2) + e2;

    float2 vals[NC];
#pragma unroll
    for (int c = 0; c < NC; c++)
        vals[c] = *(const float2*)(base + (size_t)c * stride);

    float2 run = make_float2(0.f, 0.f);
#pragma unroll
    for (int c = 0; c < NC; c++) {
        __nv_bfloat16 h0, l0, h1, l1;
        split_bf(run.x, h0, l0);
        split_bf(run.y, h1, l1);
        bh_h[(size_t)c * (stride / 2)] = pack2(h0, h1);
        bh_l[(size_t)c * (stride / 2)] = pack2(l0, l1);
        run.x += vals[c].x;
        run.y += vals[c].y;
    }
}

// ---------------------------------------------------------------------------
// Kernel 3: P = tril(Q K^T); O = Q S + P V.
// 6 smem tiles (55.3 KB): S overlays K after the P-pass via a bare uint2 copy
// of the pre-split planes (L2-resident). NO carveout override.
// ---------------------------------------------------------------------------
#define K3_QH  0
#define K3_QL  (1*TILE_B)
#define K3_KSH (2*TILE_B)   // K during P-pass, then S
#define K3_KSL (3*TILE_B)
#define K3_VH  (4*TILE_B)
#define K3_VL  (5*TILE_B)
#define K3_SMEM (6*TILE_B)  // 55296 B

__global__ __launch_bounds__(128) void out_kernel(const float* __restrict__ qg,
                                                  const float* __restrict__ kg,
                                                  const float* __restrict__ vg,
                                                  float* __restrict__ og) {
    extern __shared__ char sm[];
    const uint32_t sb = smem_u32(sm);
    const int tid = threadIdx.x, w = tid >> 5, l = tid & 31;
    const int c = blockIdx.x, bh = blockIdx.y;

    const float* qp = qg + ((size_t)bh * TT + (size_t)c * CH) * DD;
    const float* kp = kg + ((size_t)bh * TT + (size_t)c * CH) * DD;
    const float* vp = vg + ((size_t)bh * TT + (size_t)c * CH) * DD;
    const uint32_t* sph = g_sh + ((size_t)(bh * NC + c)) * (DD * DD / 2);
    const uint32_t* spl = g_sl + ((size_t)(bh * NC + c)) * (DD * DD / 2);

#pragma unroll
    for (int it = 0; it < 8; it++) {
        int idx = tid + it * 128;
        int r = idx >> 4, d0 = (idx & 15) * 4;
        const uint32_t so = (r * PIT + d0) * 2;
        uint2 hi, lo;
        split4(*(const float4*)(qp + (size_t)r * DD + d0), hi, lo);
        *(uint2*)(sm + K3_QH + so) = hi;   *(uint2*)(sm + K3_QL + so) = lo;
        split4(*(const float4*)(kp + (size_t)r * DD + d0), hi, lo);
        *(uint2*)(sm + K3_KSH + so) = hi;  *(uint2*)(sm + K3_KSL + so) = lo;
        split4(*(const float4*)(vp + (size_t)r * DD + d0), hi, lo);
        *(uint2*)(sm + K3_VH + so) = hi;   *(uint2*)(sm + K3_VL + so) = lo;
    }
    __syncthreads();

    const int m0 = w * 16;
    const int gid = l >> 2, tig = l & 3;
    const int i0 = m0 + gid;
    const uint32_t aOffN = ((m0 + (l & 15)) * PIT + ((l >> 4) << 3)) * 2;
    const uint32_t bOffN = (((l & 7) + ((l & 16) >> 1)) * PIT + ((l >> 3) & 1) * 8) * 2;
    const uint32_t bOffT = (((l & 7) + (l & 8)) * PIT + ((l >> 4) & 1) * 8) * 2;

    // ---- P = Q K^T (causal: only n-blocks j <= 16(w+1)) ----
    float accP[8][4] = {};
    {
        const uint32_t aS[3] = {K3_QH, K3_QH, K3_QL};
        const uint32_t bS[3] = {K3_KSH, K3_KSL, K3_KSH};
#pragma unroll
        for (int p = 0; p < 3; p++) {
            const uint32_t aB = sb + aS[p] + aOffN, bB = sb + bS[p] + bOffN;
#pragma unroll
            for (int ks = 0; ks < 4; ks++) {
                uint32_t a[4];
                ldsm4(aB + ks * 32, a);
#pragma unroll
                for (int nb = 0; nb < 4; nb++)
                    if (nb <= w) {
                        uint32_t b[4];
                        ldsm4(bB + nb * 16 * PIT * 2 + ks * 32, b);
                        mma16816(accP[2 * nb],     a, b[0], b[1]);
                        mma16816(accP[2 * nb + 1], a, b[2], b[3]);
                    }
            }
        }
    }

    // ---- all warps done reading K; overlay S into the K slots ----
    __syncthreads();
#pragma unroll
    for (int it = 0; it < 8; it++) {
        int idx = tid + it * 128;
        int r = idx >> 4, d0 = (idx & 15) * 4;
        const uint32_t so = (r * PIT + d0) * 2;
        const size_t si = ((size_t)r * DD + d0) / 2;
        *(uint2*)(sm + K3_KSH + so) = *(const uint2*)(sph + si);
        *(uint2*)(sm + K3_KSL + so) = *(const uint2*)(spl + si);
    }

    // ---- mask + in-register split of P to A-operand fragments (reg-only) ----
    uint32_t aPh[4][4], aPl[4][4];
#pragma unroll
    for (int nb = 0; nb < 4; nb++)
        if (nb <= w) {
#pragma unroll
            for (int s2 = 0; s2 < 2; s2++) {
                const int j0 = 16 * nb + 8 * s2 + 2 * tig;
                float c0 = (j0     <= i0)     ? accP[2 * nb + s2][0] : 0.f;
                float c1 = (j0 + 1 <= i0)     ? accP[2 * nb + s2][1] : 0.f;
                float c2 = (j0     <= i0 + 8) ? accP[2 * nb + s2][2] : 0.f;
                float c3 = (j0 + 1 <= i0 + 8) ? accP[2 * nb + s2][3] : 0.f;
                __nv_bfloat16 h0, l0, h1, l1, h2, l2, h3, l3;
                split_bf(c0, h0, l0); split_bf(c1, h1, l1);
                split_bf(c2, h2, l2); split_bf(c3, h3, l3);
                aPh[nb][2 * s2]     = pack2(h0, h1);
                aPh[nb][2 * s2 + 1] = pack2(h2, h3);
                aPl[nb][2 * s2]     = pack2(l0, l1);
                aPl[nb][2 * s2 + 1] = pack2(l2, l3);
            }
        }
    __syncthreads();

    // ---- O1 = Q @ S (B = S^T via trans loads of S[d][e]) ----
    float accO[8][4] = {};
    {
        const uint32_t aS[3] = {K3_QH, K3_QH, K3_QL};
        const uint32_t bS[3] = {K3_KSH, K3_KSL, K3_KSH};
#pragma unroll
        for (int p = 0; p < 3; p++) {
            const uint32_t aB = sb + aS[p] + aOffN, bB = sb + bS[p] + bOffT;
#pragma unroll
            for (int ks = 0; ks < 4; ks++) {
                uint32_t a[4];
                ldsm4(aB + ks * 32, a);
#pragma unroll
                for (int nb = 0; nb < 4; nb++) {
                    uint32_t b[4];
                    ldsm4t(bB + ks * 16 * PIT * 2 + nb * 32, b);
                    mma16816(accO[2 * nb],     a, b[0], b[1]);
                    mma16816(accO[2 * nb + 1], a, b[2], b[3]);
                }
            }
        }
    }

    // ---- O2 += P @ V (A = register P, B = V^T trans; causal k-blocks only) ----
    {
#pragma unroll
        for (int p = 0; p < 3; p++) {
            const uint32_t bB = sb + (p == 1 ? K3_VL : K3_VH) + bOffT;
#pragma unroll
            for (int kb = 0; kb < 4; kb++)
                if (kb <= w) {
                    const uint32_t (&a)[4] = (p < 2) ? aPh[kb] : aPl[kb];
#pragma unroll
                    for (int nb = 0; nb < 4; nb++) {
                        uint32_t b[4];
                        ldsm4t(bB + kb * 16 * PIT * 2 + nb * 32, b);
                        mma16816(accO[2 * nb],     a, b[0], b[1]);
                        mma16816(accO[2 * nb + 1], a, b[2], b[3]);
                    }
                }
        }
    }

    // ---- store O ----
    float* op = og + ((size_t)bh * TT + (size_t)c * CH) * DD;
#pragma unroll
    for (int nb8 = 0; nb8 < 8; nb8++) {
        const int e = 8 * nb8 + 2 * tig;
        *(float2*)(op + (size_t)i0 * DD + e)       = make_float2(accO[nb8][0], accO[nb8][1]);
        *(float2*)(op + (size_t)(i0 + 8) * DD + e) = make_float2(accO[nb8][2], accO[nb8][3]);
    }
}

// ---------------------------------------------------------------------------
extern "C" void kernel_launch(void* const* d_in, const int* in_sizes, int n_in,
                              void* d_out, int out_size) {
    const float* q = (const float*)d_in[0];
    const float* k = (const float*)d_in[1];
    const float* v = (const float*)d_in[2];
    float* o = (float*)d_out;

    cudaFuncSetAttribute(kv_kernel, cudaFuncAttributeMaxDynamicSharedMemorySize, K1_SMEM);
    cudaFuncSetAttribute(out_kernel, cudaFuncAttributeMaxDynamicSharedMemorySize, K3_SMEM);

    dim3 grid(NC, BH);
    kv_kernel<<<grid, 128, K1_SMEM>>>(k, v);
    prefix_kernel<<<dim3((DD * DD / 2) / 256, BH), 256>>>();
    out_kernel<<<grid, 128, K3_SMEM>>>(q, k, v, o);
}